// round 4
// baseline (speedup 1.0000x reference)
#include <cuda_runtime.h>
#include <math.h>

#define BB   128
#define TT   1024
#define DD   128
#define HH   512
#define NHID 1024
#define GRID 128
#define NTHR 256

// ---------------- scratch (static device memory; no allocations) -------------
__device__ float g_h[2][BB * HH];
__device__ float g_c[BB * HH];
__device__ float g_z[BB * HH];
__device__ float g_k[4][BB * HH];
__device__ float g_t1[BB * NHID];
__device__ float g_t2[BB * NHID];
__device__ float g_pred[BB * 5 * HH];
__device__ float g_dec1[BB * 5 * NHID];

__device__ unsigned g_cnt = 0;
__device__ volatile unsigned g_gen = 0;

// ---------------- grid-wide barrier (all 128 blocks co-resident) -------------
__device__ __forceinline__ void gsync() {
    __threadfence();
    __syncthreads();
    if (threadIdx.x == 0) {
        unsigned gen = g_gen;
        if (atomicAdd(&g_cnt, 1u) == GRID - 1) {
            g_cnt = 0;
            __threadfence();
            g_gen = gen + 1;
        } else {
            while (g_gen == gen) { }
        }
    }
    __syncthreads();
    __threadfence();
}

// ---------------- packed f32x2 FMA helpers -----------------------------------
__device__ __forceinline__ void fma2(unsigned long long& acc,
                                     unsigned long long a, unsigned long long b) {
    asm("fma.rn.f32x2 %0, %1, %2, %0;" : "+l"(acc) : "l"(a), "l"(b));
}
__device__ __forceinline__ unsigned long long pack2(float x) {
    unsigned long long r;
    asm("mov.b64 %0, {%1, %1};" : "=l"(r) : "f"(x));
    return r;
}
__device__ __forceinline__ float2 unpack2(unsigned long long v) {
    float2 r;
    asm("mov.b64 {%0, %1}, %2;" : "=f"(r.x), "=f"(r.y) : "l"(v));
    return r;
}

__device__ __forceinline__ float sigmoidf_(float x) { return 1.f / (1.f + expf(-x)); }
__device__ __forceinline__ float eluf_(float x)     { return x > 0.f ? x : expm1f(x); }

// ---------------- core K-block compute (shared for all GEMMs) ----------------
// As[32][34]: [k][row] for 32 rows. Ws[32][64]: [k][col].
// Thread (tx=tid&15, ty=tid>>4) computes rows {ty*2, ty*2+1} x cols {tx*4..+3}.
__device__ __forceinline__ void kblock_fma(
    const float (*As)[34], const float (*Ws)[64], int tx, int ty,
    unsigned long long& a0, unsigned long long& a1,
    unsigned long long& a2, unsigned long long& a3)
{
#pragma unroll
    for (int kk = 0; kk < 32; kk++) {
        float2 av = *(const float2*)&As[kk][ty * 2];
        ulonglong2 wv = *(const ulonglong2*)&Ws[kk][tx * 4];
        unsigned long long ax = pack2(av.x);
        unsigned long long ay = pack2(av.y);
        fma2(a0, ax, wv.x);
        fma2(a1, ax, wv.y);
        fma2(a2, ay, wv.x);
        fma2(a3, ay, wv.y);
    }
}

// Loaders: A-tile (32 rows x 32 k): thread (arow=tid&31, akg=tid>>5) -> float4.
// W-tile (64 cols x 32 k): thread (wn=tid&63, wkg=tid>>6) -> 8 floats.
// Both store patterns are shared-bank conflict-free.

// ---------------- generic GEMM: C[M,N] = act(Aeff @ W[N,K]^T + bias) ----------
// Aeff = A (+ alpha*A2). Tiles: BM=32, BN=64, BK=32. tile-strided over GRID.
template <int ACT, bool HASA2>
__device__ void gemm_dev(const float* __restrict__ A, const float* __restrict__ A2,
                         float alpha, const float* __restrict__ W,
                         const float* __restrict__ bias, float* __restrict__ C,
                         int M, int N, int K, float (*As)[34], float (*Ws)[64])
{
    int tid = threadIdx.x;
    int tx = tid & 15, ty = tid >> 4;
    int arow = tid & 31, akg = tid >> 5;
    int wn = tid & 63, wkg = tid >> 6;
    int ntiles = N >> 6, mtiles = M >> 5;
    int total = ntiles * mtiles;

    for (int tile = blockIdx.x; tile < total; tile += GRID) {
        int n0 = (tile % ntiles) << 6;
        int m0 = (tile / ntiles) << 5;
        const float* Arow  = A + (size_t)(m0 + arow) * K;
        const float* A2row = HASA2 ? (A2 + (size_t)(m0 + arow) * K) : A;
        const float* Wrow  = W + (size_t)(n0 + wn) * K;

        unsigned long long a0 = 0, a1 = 0, a2 = 0, a3 = 0;
        for (int kb = 0; kb < K; kb += 32) {
            float4 av = *(const float4*)(Arow + kb + akg * 4);
            if (HASA2) {
                float4 a2v = *(const float4*)(A2row + kb + akg * 4);
                av.x = fmaf(alpha, a2v.x, av.x);
                av.y = fmaf(alpha, a2v.y, av.y);
                av.z = fmaf(alpha, a2v.z, av.z);
                av.w = fmaf(alpha, a2v.w, av.w);
            }
            As[akg * 4 + 0][arow] = av.x;
            As[akg * 4 + 1][arow] = av.y;
            As[akg * 4 + 2][arow] = av.z;
            As[akg * 4 + 3][arow] = av.w;

            float4 w0 = *(const float4*)(Wrow + kb + wkg * 8);
            float4 w1 = *(const float4*)(Wrow + kb + wkg * 8 + 4);
            Ws[wkg * 8 + 0][wn] = w0.x; Ws[wkg * 8 + 1][wn] = w0.y;
            Ws[wkg * 8 + 2][wn] = w0.z; Ws[wkg * 8 + 3][wn] = w0.w;
            Ws[wkg * 8 + 4][wn] = w1.x; Ws[wkg * 8 + 5][wn] = w1.y;
            Ws[wkg * 8 + 6][wn] = w1.z; Ws[wkg * 8 + 7][wn] = w1.w;
            __syncthreads();
            kblock_fma(As, Ws, tx, ty, a0, a1, a2, a3);
            __syncthreads();
        }

        float4 bv = *(const float4*)(bias + n0 + tx * 4);
        float2 r0a = unpack2(a0), r0b = unpack2(a1);
        float2 r1a = unpack2(a2), r1b = unpack2(a3);
        float4 o0, o1;
        o0.x = r0a.x + bv.x; o0.y = r0a.y + bv.y; o0.z = r0b.x + bv.z; o0.w = r0b.y + bv.w;
        o1.x = r1a.x + bv.x; o1.y = r1a.y + bv.y; o1.z = r1b.x + bv.z; o1.w = r1b.y + bv.w;
        if (ACT == 1) {
            o0.x = eluf_(o0.x); o0.y = eluf_(o0.y); o0.z = eluf_(o0.z); o0.w = eluf_(o0.w);
            o1.x = eluf_(o1.x); o1.y = eluf_(o1.y); o1.z = eluf_(o1.z); o1.w = eluf_(o1.w);
        }
        if (ACT == 2) {
            o0.x = fmaxf(o0.x, 0.f); o0.y = fmaxf(o0.y, 0.f);
            o0.z = fmaxf(o0.z, 0.f); o0.w = fmaxf(o0.w, 0.f);
            o1.x = fmaxf(o1.x, 0.f); o1.y = fmaxf(o1.y, 0.f);
            o1.z = fmaxf(o1.z, 0.f); o1.w = fmaxf(o1.w, 0.f);
        }
        *(float4*)(C + (size_t)(m0 + ty * 2) * N + n0 + tx * 4) = o0;
        *(float4*)(C + (size_t)(m0 + ty * 2 + 1) * N + n0 + tx * 4) = o1;
    }
}

// ---------------- fused LSTM step (one tile per block, 128 tiles) ------------
// Block b: htile = b&31 (16 hidden units), mtile = b>>5 (32 batch rows).
// Columns wn in [0,64): gate g = wn>>4, unit j = wn&15 -> W row g*512 + h0 + j.
__device__ void lstm_step_dev(const float* __restrict__ x,
                              const float* __restrict__ Wih,
                              const float* __restrict__ Whh,
                              const float* __restrict__ bih,
                              const float* __restrict__ bhh,
                              const float* __restrict__ hin,
                              float* __restrict__ hout, int t,
                              float (*As)[34], float (*Ws)[64], float (*Gs)[64])
{
    int tid = threadIdx.x;
    int tx = tid & 15, ty = tid >> 4;
    int arow = tid & 31, akg = tid >> 5;
    int wn = tid & 63, wkg = tid >> 6;
    int h0 = (blockIdx.x & 31) * 16;
    int m0 = (blockIdx.x >> 5) * 32;
    int wcol = (wn >> 4) * HH + h0 + (wn & 15);

    unsigned long long a0 = 0, a1 = 0, a2 = 0, a3 = 0;

    // part 1: x_t @ W_ih^T (K = 128)
    {
        const float* Arow = x + ((size_t)(m0 + arow) * TT + t) * DD;
        const float* Wrow = Wih + (size_t)wcol * DD;
        for (int kb = 0; kb < DD; kb += 32) {
            float4 av = *(const float4*)(Arow + kb + akg * 4);
            As[akg * 4 + 0][arow] = av.x; As[akg * 4 + 1][arow] = av.y;
            As[akg * 4 + 2][arow] = av.z; As[akg * 4 + 3][arow] = av.w;
            float4 w0 = *(const float4*)(Wrow + kb + wkg * 8);
            float4 w1 = *(const float4*)(Wrow + kb + wkg * 8 + 4);
            Ws[wkg * 8 + 0][wn] = w0.x; Ws[wkg * 8 + 1][wn] = w0.y;
            Ws[wkg * 8 + 2][wn] = w0.z; Ws[wkg * 8 + 3][wn] = w0.w;
            Ws[wkg * 8 + 4][wn] = w1.x; Ws[wkg * 8 + 5][wn] = w1.y;
            Ws[wkg * 8 + 6][wn] = w1.z; Ws[wkg * 8 + 7][wn] = w1.w;
            __syncthreads();
            kblock_fma(As, Ws, tx, ty, a0, a1, a2, a3);
            __syncthreads();
        }
    }
    // part 2: h @ W_hh^T (K = 512)
    {
        const float* Arow = hin + (size_t)(m0 + arow) * HH;
        const float* Wrow = Whh + (size_t)wcol * HH;
        for (int kb = 0; kb < HH; kb += 32) {
            float4 av = *(const float4*)(Arow + kb + akg * 4);
            As[akg * 4 + 0][arow] = av.x; As[akg * 4 + 1][arow] = av.y;
            As[akg * 4 + 2][arow] = av.z; As[akg * 4 + 3][arow] = av.w;
            float4 w0 = *(const float4*)(Wrow + kb + wkg * 8);
            float4 w1 = *(const float4*)(Wrow + kb + wkg * 8 + 4);
            Ws[wkg * 8 + 0][wn] = w0.x; Ws[wkg * 8 + 1][wn] = w0.y;
            Ws[wkg * 8 + 2][wn] = w0.z; Ws[wkg * 8 + 3][wn] = w0.w;
            Ws[wkg * 8 + 4][wn] = w1.x; Ws[wkg * 8 + 5][wn] = w1.y;
            Ws[wkg * 8 + 6][wn] = w1.z; Ws[wkg * 8 + 7][wn] = w1.w;
            __syncthreads();
            kblock_fma(As, Ws, tx, ty, a0, a1, a2, a3);
            __syncthreads();
        }
    }

    // gates -> shared with bias
    {
        int g = (tx * 4) >> 4;
        int j0 = (tx * 4) & 15;
        int bbase = g * HH + h0 + j0;
        float4 bi = *(const float4*)(bih + bbase);
        float4 bh = *(const float4*)(bhh + bbase);
        float2 r0a = unpack2(a0), r0b = unpack2(a1);
        float2 r1a = unpack2(a2), r1b = unpack2(a3);
        float4 g0, g1;
        g0.x = r0a.x + bi.x + bh.x; g0.y = r0a.y + bi.y + bh.y;
        g0.z = r0b.x + bi.z + bh.z; g0.w = r0b.y + bi.w + bh.w;
        g1.x = r1a.x + bi.x + bh.x; g1.y = r1a.y + bi.y + bh.y;
        g1.z = r1b.x + bi.z + bh.z; g1.w = r1b.y + bi.w + bh.w;
        *(float4*)&Gs[ty * 2][tx * 4]     = g0;
        *(float4*)&Gs[ty * 2 + 1][tx * 4] = g1;
    }
    __syncthreads();

    // elementwise c/h update: 512 elems, 2 per thread
#pragma unroll
    for (int q = 0; q < 2; q++) {
        int il = q * NTHR + tid;
        int rr = il >> 4, jj = il & 15;
        float iv = sigmoidf_(Gs[rr][jj]);
        float fv = sigmoidf_(Gs[rr][16 + jj]);
        float gv = tanhf(Gs[rr][32 + jj]);
        float ov = sigmoidf_(Gs[rr][48 + jj]);
        int idx = (m0 + rr) * HH + h0 + jj;
        float cn = fv * g_c[idx] + iv * gv;
        g_c[idx] = cn;
        hout[idx] = ov * tanhf(cn);
    }
    __syncthreads();
}

// ---------------- mega persistent kernel (single graph node) -----------------
__global__ __launch_bounds__(NTHR) void mega_kernel(
    const float* __restrict__ x,
    const float* __restrict__ Wih, const float* __restrict__ Whh,
    const float* __restrict__ bih, const float* __restrict__ bhh,
    const float* __restrict__ ow1, const float* __restrict__ ob1,
    const float* __restrict__ ow2, const float* __restrict__ ob2,
    const float* __restrict__ ow3, const float* __restrict__ ob3,
    const float* __restrict__ dw1, const float* __restrict__ db1,
    const float* __restrict__ dw2, const float* __restrict__ db2,
    float* __restrict__ out)
{
    __shared__ float As[32][34];
    __shared__ float Ws[32][64];
    __shared__ float Gs[32][64];

    int tid = threadIdx.x;
    int gidx = blockIdx.x * NTHR + tid;   // 32768 threads, 2 elems each of 65536

    // ---- init h0, c0 ----
    g_h[0][gidx] = 0.f; g_h[0][gidx + GRID * NTHR] = 0.f;
    g_c[gidx] = 0.f;    g_c[gidx + GRID * NTHR] = 0.f;
    gsync();

    // ---- LSTM encoder: 1024 steps ----
    for (int t = 0; t < TT; t++) {
        const float* hin = (t & 1) ? g_h[1] : g_h[0];
        float* hout      = (t & 1) ? g_h[0] : g_h[1];
        lstm_step_dev(x, Wih, Whh, bih, bhh, hin, hout, t, As, Ws, Gs);
        gsync();
    }

    // ---- z0 = c_n; pred slot 0 ----
#pragma unroll
    for (int q = 0; q < 2; q++) {
        int e = gidx + q * GRID * NTHR;
        float v = g_c[e];
        g_z[e] = v;
        int b = e >> 9, h = e & 511;
        g_pred[(b * 5) * HH + h] = v;
    }
    gsync();

    // ---- latent ODE: 32 RK4 substeps ----
    const double dtd = (5.0 / 60.0) / 8.0;
    const float dtf  = (float)dtd;
    const float half = (float)(0.5 * dtd);
    const float dt6  = (float)(dtd / 6.0);

    for (int step = 0; step < 32; step++) {
        // k1 = f(z)
        gemm_dev<1, false>(g_z, nullptr, 0.f, ow1, ob1, g_t1, BB, NHID, HH, As, Ws); gsync();
        gemm_dev<1, false>(g_t1, nullptr, 0.f, ow2, ob2, g_t2, BB, NHID, NHID, As, Ws); gsync();
        gemm_dev<0, false>(g_t2, nullptr, 0.f, ow3, ob3, g_k[0], BB, HH, NHID, As, Ws); gsync();
        // k2 = f(z + 0.5 dt k1)
        gemm_dev<1, true>(g_z, g_k[0], half, ow1, ob1, g_t1, BB, NHID, HH, As, Ws); gsync();
        gemm_dev<1, false>(g_t1, nullptr, 0.f, ow2, ob2, g_t2, BB, NHID, NHID, As, Ws); gsync();
        gemm_dev<0, false>(g_t2, nullptr, 0.f, ow3, ob3, g_k[1], BB, HH, NHID, As, Ws); gsync();
        // k3 = f(z + 0.5 dt k2)
        gemm_dev<1, true>(g_z, g_k[1], half, ow1, ob1, g_t1, BB, NHID, HH, As, Ws); gsync();
        gemm_dev<1, false>(g_t1, nullptr, 0.f, ow2, ob2, g_t2, BB, NHID, NHID, As, Ws); gsync();
        gemm_dev<0, false>(g_t2, nullptr, 0.f, ow3, ob3, g_k[2], BB, HH, NHID, As, Ws); gsync();
        // k4 = f(z + dt k3)
        gemm_dev<1, true>(g_z, g_k[2], dtf, ow1, ob1, g_t1, BB, NHID, HH, As, Ws); gsync();
        gemm_dev<1, false>(g_t1, nullptr, 0.f, ow2, ob2, g_t2, BB, NHID, NHID, As, Ws); gsync();
        gemm_dev<0, false>(g_t2, nullptr, 0.f, ow3, ob3, g_k[3], BB, HH, NHID, As, Ws); gsync();
        // combine
#pragma unroll
        for (int q = 0; q < 2; q++) {
            int e = gidx + q * GRID * NTHR;
            float z = g_z[e] + dt6 * (g_k[0][e] + 2.f * (g_k[1][e] + g_k[2][e]) + g_k[3][e]);
            g_z[e] = z;
            if ((step & 7) == 7) {
                int b = e >> 9, h = e & 511;
                g_pred[(b * 5 + (step >> 3) + 1) * HH + h] = z;
            }
        }
        gsync();
    }

    // ---- decoder ----
    gemm_dev<2, false>(g_pred, nullptr, 0.f, dw1, db1, g_dec1, BB * 5, NHID, HH, As, Ws);
    gsync();
    gemm_dev<0, false>(g_dec1, nullptr, 0.f, dw2, db2, out, BB * 5, DD, NHID, As, Ws);
}

// ---------------- host side ---------------------------------------------------
extern "C" void kernel_launch(void* const* d_in, const int* in_sizes, int n_in,
                              void* d_out, int out_size)
{
    const float* inputs = (const float*)d_in[0];

    // Locate W_ih robustly: 4*512*128 elems followed by 4*512*512.
    int p = 2;
    for (int i = 1; i + 1 < n_in; i++) {
        if (in_sizes[i] == 4 * HH * DD && in_sizes[i + 1] == 4 * HH * HH) { p = i; break; }
    }
    const float* W_ih  = (const float*)d_in[p + 0];
    const float* W_hh  = (const float*)d_in[p + 1];
    const float* b_ih  = (const float*)d_in[p + 2];
    const float* b_hh  = (const float*)d_in[p + 3];
    const float* ow1 = (const float*)d_in[p + 4];
    const float* ob1 = (const float*)d_in[p + 5];
    const float* ow2 = (const float*)d_in[p + 6];
    const float* ob2 = (const float*)d_in[p + 7];
    const float* ow3 = (const float*)d_in[p + 8];
    const float* ob3 = (const float*)d_in[p + 9];
    const float* dw1 = (const float*)d_in[p + 10];
    const float* db1 = (const float*)d_in[p + 11];
    const float* dw2 = (const float*)d_in[p + 12];
    const float* db2 = (const float*)d_in[p + 13];

    mega_kernel<<<GRID, NTHR>>>(inputs, W_ih, W_hh, b_ih, b_hh,
                                ow1, ob1, ow2, ob2, ow3, ob3,
                                dw1, db1, dw2, db2, (float*)d_out);
}

// round 5
// speedup vs baseline: 1.0760x; 1.0760x over previous
#include <cuda_runtime.h>
#include <math.h>

#define BB   128
#define TT   1024
#define DD   128
#define HH   512
#define NHID 1024
#define GRID 128
#define NTHR 512

typedef unsigned long long ull;

// ---------------- scratch (static device memory; no allocations) -------------
__device__ float g_h[2][BB * HH];
__device__ float g_c[BB * HH];
__device__ float g_z[BB * HH];
__device__ float g_k[4][BB * HH];
__device__ float g_t1[BB * NHID];
__device__ float g_t2[BB * NHID];
__device__ float g_pred[BB * 5 * HH];
__device__ float g_dec1[BB * 5 * NHID];

__device__ unsigned g_cnt = 0;
__device__ volatile unsigned g_gen = 0;

// ---------------- grid-wide barrier (128 blocks, all co-resident) ------------
__device__ __forceinline__ void gsync() {
    __threadfence();
    __syncthreads();
    if (threadIdx.x == 0) {
        unsigned gen = g_gen;
        if (atomicAdd(&g_cnt, 1u) == GRID - 1) {
            g_cnt = 0;
            __threadfence();
            g_gen = gen + 1;
        } else {
            while (g_gen == gen) { }
        }
    }
    __syncthreads();
    __threadfence();
}

// ---------------- packed f32x2 helpers ----------------------------------------
__device__ __forceinline__ void fma2(ull& acc, ull a, ull b) {
    asm("fma.rn.f32x2 %0, %1, %2, %0;" : "+l"(acc) : "l"(a), "l"(b));
}
__device__ __forceinline__ ull addf2(ull a, ull b) {
    ull r; asm("add.rn.f32x2 %0, %1, %2;" : "=l"(r) : "l"(a), "l"(b)); return r;
}
__device__ __forceinline__ ull pack2(float x) {
    ull r; asm("mov.b64 %0, {%1, %1};" : "=l"(r) : "f"(x)); return r;
}
__device__ __forceinline__ float2 unpack2(ull v) {
    float2 r; asm("mov.b64 {%0, %1}, %2;" : "=f"(r.x), "=f"(r.y) : "l"(v)); return r;
}
__device__ __forceinline__ float sigmoidf_(float x) { return 1.f / (1.f + expf(-x)); }
__device__ __forceinline__ float eluf_(float x)     { return x > 0.f ? x : expm1f(x); }

// group barrier: group 0 = warps 0-7 (barrier 1), group 1 = warps 8-15 (barrier 2)
__device__ __forceinline__ void gbar(int grp) {
    asm volatile("bar.sync %0, 256;" :: "r"(grp + 1) : "memory");
}

// ---------------- shared tile buffers ------------------------------------------
// As2: A values duplicated into 64-bit lanes -> FFMA2 operand needs no pack MOV.
struct __align__(16) Buf {
    ull   As2[32][34];   // [k][row], row-pair LDS.128 gives {a0,a0,a1,a1}
    float Ws[32][64];    // [k][col]
};

// ---------------- tile stores ---------------------------------------------------
__device__ __forceinline__ void stA(Buf& b, float4 av, int akg, int arow) {
    b.As2[akg * 4 + 0][arow] = pack2(av.x);
    b.As2[akg * 4 + 1][arow] = pack2(av.y);
    b.As2[akg * 4 + 2][arow] = pack2(av.z);
    b.As2[akg * 4 + 3][arow] = pack2(av.w);
}
__device__ __forceinline__ void stW(Buf& b, float4 w0, float4 w1, int wkg, int wn) {
    b.Ws[wkg * 8 + 0][wn] = w0.x; b.Ws[wkg * 8 + 1][wn] = w0.y;
    b.Ws[wkg * 8 + 2][wn] = w0.z; b.Ws[wkg * 8 + 3][wn] = w0.w;
    b.Ws[wkg * 8 + 4][wn] = w1.x; b.Ws[wkg * 8 + 5][wn] = w1.y;
    b.Ws[wkg * 8 + 6][wn] = w1.z; b.Ws[wkg * 8 + 7][wn] = w1.w;
}

// ---------------- k-block compute: 6 instr per 8 MACs ---------------------------
__device__ __forceinline__ void kfma(const Buf& b, int tx, int ty,
                                     ull& a0, ull& a1, ull& a2, ull& a3) {
#pragma unroll
    for (int kk = 0; kk < 32; kk++) {
        ulonglong2 av = *(const ulonglong2*)&b.As2[kk][ty * 2];
        ulonglong2 wv = *(const ulonglong2*)&b.Ws[kk][tx * 4];
        fma2(a0, av.x, wv.x);
        fma2(a1, av.x, wv.y);
        fma2(a2, av.y, wv.x);
        fma2(a3, av.y, wv.y);
    }
}

// ---------------- generic GEMM: C[M,N] = act(Aeff @ W[N,K]^T + bias) ------------
// Tile BM=32, BN=64, split-K x2 across thread groups. Aeff = A (+ alpha*A2).
template <int ACT, bool HASA2>
__device__ void gemm2(Buf* bufs, const float* __restrict__ A,
                      const float* __restrict__ A2, float alpha,
                      const float* __restrict__ W, const float* __restrict__ bias,
                      float* __restrict__ C, int M, int N, int K)
{
    int tid = threadIdx.x, grp = tid >> 8, ltid = tid & 255;
    int tx = ltid & 15, ty = ltid >> 4;
    int arow = ltid & 31, akg = ltid >> 5;
    int wn = ltid & 63, wkg = ltid >> 6;
    Buf& b = bufs[grp];
    ull* red = &bufs[1].As2[0][0];   // reused as reduction buffer (1024 ulls fit)
    int ntiles = N >> 6, total = ntiles * (M >> 5);
    int khalf = K >> 1, nkb = khalf >> 5;

    for (int tile = blockIdx.x; tile < total; tile += GRID) {
        int n0 = (tile % ntiles) << 6;
        int m0 = (tile / ntiles) << 5;
        const float* Ar  = A + (size_t)(m0 + arow) * K + (size_t)grp * khalf + akg * 4;
        const float* A2r = HASA2 ? (A2 + (size_t)(m0 + arow) * K + (size_t)grp * khalf + akg * 4) : nullptr;
        const float* Wr  = W + (size_t)(n0 + wn) * K + (size_t)grp * khalf + wkg * 8;

        // prefetch k-block 0
        float4 av = *(const float4*)Ar;
        if (HASA2) {
            float4 v2 = *(const float4*)A2r;
            av.x = fmaf(alpha, v2.x, av.x); av.y = fmaf(alpha, v2.y, av.y);
            av.z = fmaf(alpha, v2.z, av.z); av.w = fmaf(alpha, v2.w, av.w);
        }
        float4 w0 = *(const float4*)Wr;
        float4 w1 = *(const float4*)(Wr + 4);

        ull a0 = 0, a1 = 0, a2 = 0, a3 = 0;
        for (int kb = 0; kb < nkb; kb++) {
            stA(b, av, akg, arow);
            stW(b, w0, w1, wkg, wn);
            gbar(grp);
            if (kb + 1 < nkb) {                 // prefetch next while computing
                av = *(const float4*)(Ar + (kb + 1) * 32);
                if (HASA2) {
                    float4 v2 = *(const float4*)(A2r + (kb + 1) * 32);
                    av.x = fmaf(alpha, v2.x, av.x); av.y = fmaf(alpha, v2.y, av.y);
                    av.z = fmaf(alpha, v2.z, av.z); av.w = fmaf(alpha, v2.w, av.w);
                }
                w0 = *(const float4*)(Wr + (kb + 1) * 32);
                w1 = *(const float4*)(Wr + (kb + 1) * 32 + 4);
            }
            kfma(b, tx, ty, a0, a1, a2, a3);
            gbar(grp);
        }

        // split-K reduction: group1 -> smem, group0 adds + epilogue
        if (grp == 1) {
            *(ulonglong2*)&red[ltid * 4]     = make_ulonglong2(a0, a1);
            *(ulonglong2*)&red[ltid * 4 + 2] = make_ulonglong2(a2, a3);
        }
        __syncthreads();
        if (grp == 0) {
            ulonglong2 r01 = *(const ulonglong2*)&red[ltid * 4];
            ulonglong2 r23 = *(const ulonglong2*)&red[ltid * 4 + 2];
            a0 = addf2(a0, r01.x); a1 = addf2(a1, r01.y);
            a2 = addf2(a2, r23.x); a3 = addf2(a3, r23.y);
            float4 bv = *(const float4*)(bias + n0 + tx * 4);
            float2 r0a = unpack2(a0), r0b = unpack2(a1);
            float2 r1a = unpack2(a2), r1b = unpack2(a3);
            float4 o0 = make_float4(r0a.x + bv.x, r0a.y + bv.y, r0b.x + bv.z, r0b.y + bv.w);
            float4 o1 = make_float4(r1a.x + bv.x, r1a.y + bv.y, r1b.x + bv.z, r1b.y + bv.w);
            if (ACT == 1) {
                o0.x = eluf_(o0.x); o0.y = eluf_(o0.y); o0.z = eluf_(o0.z); o0.w = eluf_(o0.w);
                o1.x = eluf_(o1.x); o1.y = eluf_(o1.y); o1.z = eluf_(o1.z); o1.w = eluf_(o1.w);
            }
            if (ACT == 2) {
                o0.x = fmaxf(o0.x, 0.f); o0.y = fmaxf(o0.y, 0.f);
                o0.z = fmaxf(o0.z, 0.f); o0.w = fmaxf(o0.w, 0.f);
                o1.x = fmaxf(o1.x, 0.f); o1.y = fmaxf(o1.y, 0.f);
                o1.z = fmaxf(o1.z, 0.f); o1.w = fmaxf(o1.w, 0.f);
            }
            *(float4*)(C + (size_t)(m0 + ty * 2) * N + n0 + tx * 4) = o0;
            *(float4*)(C + (size_t)(m0 + ty * 2 + 1) * N + n0 + tx * 4) = o1;
        }
        __syncthreads();
    }
}

// ---------------- fused LSTM step (1 tile / block, 128 tiles, split-K x2) ------
// Block b: h-tile = b&31 (16 units), batch-tile = b>>5 (32 rows).
// Virtual K = 640: kb 0..3 -> x/W_ih, kb 4..19 -> h/W_hh. grp0: kb 0..9, grp1: 10..19.
__device__ void lstm2(Buf* bufs, float (*Gs)[64],
                      const float* __restrict__ x, const float* __restrict__ Wih,
                      const float* __restrict__ Whh, const float* __restrict__ bih,
                      const float* __restrict__ bhh, const float* __restrict__ hin,
                      float* __restrict__ hout, int t)
{
    int tid = threadIdx.x, grp = tid >> 8, ltid = tid & 255;
    int tx = ltid & 15, ty = ltid >> 4;
    int arow = ltid & 31, akg = ltid >> 5;
    int wn = ltid & 63, wkg = ltid >> 6;
    Buf& b = bufs[grp];
    ull* red = &bufs[1].As2[0][0];
    int h0 = (blockIdx.x & 31) * 16;
    int m0 = (blockIdx.x >> 5) * 32;
    int wcol = (wn >> 4) * HH + h0 + (wn & 15);

    const float* xrow  = x + ((size_t)(m0 + arow) * TT + t) * DD + akg * 4;
    const float* hrow  = hin + (size_t)(m0 + arow) * HH + akg * 4;
    const float* wihr  = Wih + (size_t)wcol * DD + wkg * 8;
    const float* whhr  = Whh + (size_t)wcol * HH + wkg * 8;

    auto ldA  = [&](int kb) { return kb < 4 ? *(const float4*)(xrow + kb * 32)
                                            : *(const float4*)(hrow + (kb - 4) * 32); };
    auto ldW0 = [&](int kb) { return kb < 4 ? *(const float4*)(wihr + kb * 32)
                                            : *(const float4*)(whhr + (kb - 4) * 32); };
    auto ldW1 = [&](int kb) { return kb < 4 ? *(const float4*)(wihr + kb * 32 + 4)
                                            : *(const float4*)(whhr + (kb - 4) * 32 + 4); };

    int kb0 = grp * 10, kb1 = kb0 + 10;
    float4 av = ldA(kb0), w0 = ldW0(kb0), w1 = ldW1(kb0);
    ull a0 = 0, a1 = 0, a2 = 0, a3 = 0;
    for (int kb = kb0; kb < kb1; kb++) {
        stA(b, av, akg, arow);
        stW(b, w0, w1, wkg, wn);
        gbar(grp);
        if (kb + 1 < kb1) { av = ldA(kb + 1); w0 = ldW0(kb + 1); w1 = ldW1(kb + 1); }
        kfma(b, tx, ty, a0, a1, a2, a3);
        gbar(grp);
    }

    if (grp == 1) {
        *(ulonglong2*)&red[ltid * 4]     = make_ulonglong2(a0, a1);
        *(ulonglong2*)&red[ltid * 4 + 2] = make_ulonglong2(a2, a3);
    }
    __syncthreads();
    if (grp == 0) {
        ulonglong2 r01 = *(const ulonglong2*)&red[ltid * 4];
        ulonglong2 r23 = *(const ulonglong2*)&red[ltid * 4 + 2];
        a0 = addf2(a0, r01.x); a1 = addf2(a1, r01.y);
        a2 = addf2(a2, r23.x); a3 = addf2(a3, r23.y);
        int g = (tx * 4) >> 4, j0 = (tx * 4) & 15;
        int bbase = g * HH + h0 + j0;
        float4 bi = *(const float4*)(bih + bbase);
        float4 bh = *(const float4*)(bhh + bbase);
        float2 r0a = unpack2(a0), r0b = unpack2(a1);
        float2 r1a = unpack2(a2), r1b = unpack2(a3);
        float4 g0 = make_float4(r0a.x + bi.x + bh.x, r0a.y + bi.y + bh.y,
                                r0b.x + bi.z + bh.z, r0b.y + bi.w + bh.w);
        float4 g1 = make_float4(r1a.x + bi.x + bh.x, r1a.y + bi.y + bh.y,
                                r1b.x + bi.z + bh.z, r1b.y + bi.w + bh.w);
        *(float4*)&Gs[ty * 2][tx * 4]     = g0;
        *(float4*)&Gs[ty * 2 + 1][tx * 4] = g1;
    }
    __syncthreads();

    // elementwise c/h update: 512 elems, exactly 1 per thread
    int rr = tid >> 4, jj = tid & 15;
    float iv = sigmoidf_(Gs[rr][jj]);
    float fv = sigmoidf_(Gs[rr][16 + jj]);
    float gv = tanhf(Gs[rr][32 + jj]);
    float ov = sigmoidf_(Gs[rr][48 + jj]);
    int idx = (m0 + rr) * HH + h0 + jj;
    float cn = fv * g_c[idx] + iv * gv;
    g_c[idx] = cn;
    hout[idx] = ov * tanhf(cn);
    __syncthreads();
}

// ---------------- mega persistent kernel (single graph node) -------------------
__global__ __launch_bounds__(NTHR) void mega_kernel(
    const float* __restrict__ x,
    const float* __restrict__ Wih, const float* __restrict__ Whh,
    const float* __restrict__ bih, const float* __restrict__ bhh,
    const float* __restrict__ ow1, const float* __restrict__ ob1,
    const float* __restrict__ ow2, const float* __restrict__ ob2,
    const float* __restrict__ ow3, const float* __restrict__ ob3,
    const float* __restrict__ dw1, const float* __restrict__ db1,
    const float* __restrict__ dw2, const float* __restrict__ db2,
    float* __restrict__ out)
{
    __shared__ Buf bufs[2];
    __shared__ float Gs[32][64];

    int tid = threadIdx.x;
    int gidx = blockIdx.x * NTHR + tid;   // 65536 threads == BB*HH

    // ---- init h0, c0 ----
    g_h[0][gidx] = 0.f;
    g_c[gidx] = 0.f;
    gsync();

    // ---- LSTM encoder: 1024 steps ----
    for (int t = 0; t < TT; t++) {
        const float* hin = (t & 1) ? g_h[1] : g_h[0];
        float* hout      = (t & 1) ? g_h[0] : g_h[1];
        lstm2(bufs, Gs, x, Wih, Whh, bih, bhh, hin, hout, t);
        gsync();
    }

    // ---- z0 = c_n; pred slot 0 ----
    {
        float v = g_c[gidx];
        g_z[gidx] = v;
        int bb = gidx >> 9, hh = gidx & 511;
        g_pred[(bb * 5) * HH + hh] = v;
    }
    gsync();

    // ---- latent ODE: 32 RK4 substeps ----
    const double dtd = (5.0 / 60.0) / 8.0;
    const float dtf  = (float)dtd;
    const float half = (float)(0.5 * dtd);
    const float dt6  = (float)(dtd / 6.0);

    for (int step = 0; step < 32; step++) {
        gemm2<1, false>(bufs, g_z, nullptr, 0.f, ow1, ob1, g_t1, BB, NHID, HH); gsync();
        gemm2<1, false>(bufs, g_t1, nullptr, 0.f, ow2, ob2, g_t2, BB, NHID, NHID); gsync();
        gemm2<0, false>(bufs, g_t2, nullptr, 0.f, ow3, ob3, g_k[0], BB, HH, NHID); gsync();

        gemm2<1, true>(bufs, g_z, g_k[0], half, ow1, ob1, g_t1, BB, NHID, HH); gsync();
        gemm2<1, false>(bufs, g_t1, nullptr, 0.f, ow2, ob2, g_t2, BB, NHID, NHID); gsync();
        gemm2<0, false>(bufs, g_t2, nullptr, 0.f, ow3, ob3, g_k[1], BB, HH, NHID); gsync();

        gemm2<1, true>(bufs, g_z, g_k[1], half, ow1, ob1, g_t1, BB, NHID, HH); gsync();
        gemm2<1, false>(bufs, g_t1, nullptr, 0.f, ow2, ob2, g_t2, BB, NHID, NHID); gsync();
        gemm2<0, false>(bufs, g_t2, nullptr, 0.f, ow3, ob3, g_k[2], BB, HH, NHID); gsync();

        gemm2<1, true>(bufs, g_z, g_k[2], dtf, ow1, ob1, g_t1, BB, NHID, HH); gsync();
        gemm2<1, false>(bufs, g_t1, nullptr, 0.f, ow2, ob2, g_t2, BB, NHID, NHID); gsync();
        gemm2<0, false>(bufs, g_t2, nullptr, 0.f, ow3, ob3, g_k[3], BB, HH, NHID); gsync();

        {
            float z = g_z[gidx] + dt6 * (g_k[0][gidx] + 2.f * (g_k[1][gidx] + g_k[2][gidx]) + g_k[3][gidx]);
            g_z[gidx] = z;
            if ((step & 7) == 7) {
                int bb = gidx >> 9, hh = gidx & 511;
                g_pred[(bb * 5 + (step >> 3) + 1) * HH + hh] = z;
            }
        }
        gsync();
    }

    // ---- decoder ----
    gemm2<2, false>(bufs, g_pred, nullptr, 0.f, dw1, db1, g_dec1, BB * 5, NHID, HH);
    gsync();
    gemm2<0, false>(bufs, g_dec1, nullptr, 0.f, dw2, db2, out, BB * 5, DD, NHID);
}

// ---------------- host side -----------------------------------------------------
extern "C" void kernel_launch(void* const* d_in, const int* in_sizes, int n_in,
                              void* d_out, int out_size)
{
    const float* inputs = (const float*)d_in[0];

    // Locate W_ih robustly: 4*512*128 elems followed by 4*512*512.
    int p = 2;
    for (int i = 1; i + 1 < n_in; i++) {
        if (in_sizes[i] == 4 * HH * DD && in_sizes[i + 1] == 4 * HH * HH) { p = i; break; }
    }
    const float* W_ih = (const float*)d_in[p + 0];
    const float* W_hh = (const float*)d_in[p + 1];
    const float* b_ih = (const float*)d_in[p + 2];
    const float* b_hh = (const float*)d_in[p + 3];
    const float* ow1 = (const float*)d_in[p + 4];
    const float* ob1 = (const float*)d_in[p + 5];
    const float* ow2 = (const float*)d_in[p + 6];
    const float* ob2 = (const float*)d_in[p + 7];
    const float* ow3 = (const float*)d_in[p + 8];
    const float* ob3 = (const float*)d_in[p + 9];
    const float* dw1 = (const float*)d_in[p + 10];
    const float* db1 = (const float*)d_in[p + 11];
    const float* dw2 = (const float*)d_in[p + 12];
    const float* db2 = (const float*)d_in[p + 13];

    mega_kernel<<<GRID, NTHR>>>(inputs, W_ih, W_hh, b_ih, b_hh,
                                ow1, ob1, ow2, ob2, ow3, ob3,
                                dw1, db1, dw2, db2, (float*)d_out);
}

// round 6
// speedup vs baseline: 1.5622x; 1.4518x over previous
#include <cuda_runtime.h>
#include <math.h>

#define BB   128
#define TT   1024
#define DD   128
#define HH   512
#define NHID 1024
#define GRID 128
#define NTHR 512
#define NGRP 4

typedef unsigned long long ull;

// dynamic smem layout: per group 6144 floats:
//   [A0:1024][A1:1024][W0:2048][W1:2048]   (A: 32k x 32row, W: 32k x 64col)
#define A_BUF 1024
#define W_BUF 2048
#define GRP_F (2 * A_BUF + 2 * W_BUF)
#define DYN_F (NGRP * GRP_F)
#define DYN_BYTES (DYN_F * 4)

// ---------------- scratch (static device memory; no allocations) -------------
__device__ float g_h[2][BB * HH];
__device__ float g_c[BB * HH];
__device__ float g_z[BB * HH];
__device__ float g_k[4][BB * HH];
__device__ float g_t1[BB * NHID];
__device__ float g_t2[BB * NHID];
__device__ float g_pred[BB * 5 * HH];
__device__ float g_dec1[BB * 5 * NHID];

__device__ unsigned g_cnt = 0;
__device__ volatile unsigned g_gen = 0;

// ---------------- grid-wide barrier ------------------------------------------
__device__ __forceinline__ void gsync() {
    __threadfence();
    __syncthreads();
    if (threadIdx.x == 0) {
        unsigned gen = g_gen;
        if (atomicAdd(&g_cnt, 1u) == GRID - 1) {
            g_cnt = 0;
            __threadfence();
            g_gen = gen + 1;
        } else {
            while (g_gen == gen) { }
        }
    }
    __syncthreads();
    __threadfence();
}

// ---------------- packed f32x2 helpers ----------------------------------------
__device__ __forceinline__ void fma2(ull& acc, ull a, ull b) {
    asm("fma.rn.f32x2 %0, %1, %2, %0;" : "+l"(acc) : "l"(a), "l"(b));
}
__device__ __forceinline__ ull addf2(ull a, ull b) {
    ull r; asm("add.rn.f32x2 %0, %1, %2;" : "=l"(r) : "l"(a), "l"(b)); return r;
}
__device__ __forceinline__ ull pack2(float x) {
    ull r; asm("mov.b64 %0, {%1, %1};" : "=l"(r) : "f"(x)); return r;
}
__device__ __forceinline__ float2 unpack2(ull v) {
    float2 r; asm("mov.b64 {%0, %1}, %2;" : "=f"(r.x), "=f"(r.y) : "l"(v)); return r;
}
__device__ __forceinline__ float sigmoidf_(float x) { return 1.f / (1.f + expf(-x)); }
__device__ __forceinline__ float eluf_(float x)     { return x > 0.f ? x : expm1f(x); }

// named barrier per 128-thread group (ids 1..4; 0 is __syncthreads)
__device__ __forceinline__ void gbar(int grp) {
    asm volatile("bar.sync %0, 128;" :: "r"(grp + 1) : "memory");
}

// ---------------- tile store helpers ------------------------------------------
// A store: transpose [row][4k] reg -> smem A[k][row]
__device__ __forceinline__ void stA(float* Ab, float4 v, int kq, int r) {
    Ab[(kq * 4 + 0) * 32 + r] = v.x;
    Ab[(kq * 4 + 1) * 32 + r] = v.y;
    Ab[(kq * 4 + 2) * 32 + r] = v.z;
    Ab[(kq * 4 + 3) * 32 + r] = v.w;
}
__device__ __forceinline__ void stW(float* Wb, float4 v, int kq, int c) {
    Wb[(kq * 4 + 0) * 64 + c] = v.x;
    Wb[(kq * 4 + 1) * 64 + c] = v.y;
    Wb[(kq * 4 + 2) * 64 + c] = v.z;
    Wb[(kq * 4 + 3) * 64 + c] = v.w;
}

// ---------------- 32-k compute: acc[r*2+p] = col-pair p of row r ---------------
__device__ __forceinline__ void kfma32(const float* Ab, const float* Wb,
                                       int tx, int ty, ull* acc) {
#pragma unroll
    for (int k = 0; k < 32; k++) {
        float4 a = *(const float4*)&Ab[k * 32 + 4 * ty];
        ulonglong2 w = *(const ulonglong2*)&Wb[k * 64 + 4 * tx];
        ull ax = pack2(a.x), ay = pack2(a.y), az = pack2(a.z), aw = pack2(a.w);
        fma2(acc[0], ax, w.x); fma2(acc[1], ax, w.y);
        fma2(acc[2], ay, w.x); fma2(acc[3], ay, w.y);
        fma2(acc[4], az, w.x); fma2(acc[5], az, w.y);
        fma2(acc[6], aw, w.x); fma2(acc[7], aw, w.y);
    }
}

// ---------------- split-K reduction + helpers ----------------------------------
// groups 1..3 dump 8 ull partials each into their own (now-free) tile area,
// layout [i][ltid] to stay bank-friendly; group 0 accumulates.
__device__ __forceinline__ void red_write(float* dyn, int grp, int ltid, ull* acc) {
    ull* rg = (ull*)(dyn + grp * GRP_F);
#pragma unroll
    for (int i = 0; i < 8; i++) rg[i * 128 + ltid] = acc[i];
}
__device__ __forceinline__ void red_accum(float* dyn, int ltid, ull* acc) {
#pragma unroll
    for (int g = 1; g < NGRP; g++) {
        ull* rg = (ull*)(dyn + g * GRP_F);
#pragma unroll
        for (int i = 0; i < 8; i++) acc[i] = addf2(acc[i], rg[i * 128 + ltid]);
    }
}

// ---------------- generic GEMM: C[M,N] = act(Aeff @ W[N,K]^T + bias) -----------
// BM=32, BN=64, split-K x4, thread tile 4x4, double-buffered, 1 bar/kblock.
template <int ACT, bool HASA2>
__device__ void gemm4(float* dyn, const float* __restrict__ A,
                      const float* __restrict__ A2, float alpha,
                      const float* __restrict__ W, const float* __restrict__ bias,
                      float* __restrict__ C, int M, int N, int K)
{
    int tid = threadIdx.x;
    int grp = tid >> 7, ltid = tid & 127;
    int tx = ltid & 15, ty = ltid >> 4;
    int lr = ltid >> 3, lkq = ltid & 7;
    float* gd = dyn + grp * GRP_F;
    int kgrp = K >> 2;
    int nkb = kgrp >> 5;
    int koff0 = grp * kgrp + lkq * 4;
    int ntiles = N >> 6;
    int total = ntiles * (M >> 5);

    for (int tile = blockIdx.x; tile < total; tile += GRID) {
        int n0 = (tile % ntiles) << 6;
        int m0 = (tile / ntiles) << 5;

        ull acc[8];
#pragma unroll
        for (int i = 0; i < 8; i++) acc[i] = 0;

        float4 av[2], wv[4];
        // prefetch kb 0
#pragma unroll
        for (int j = 0; j < 2; j++) {
            const float* p = A + (size_t)(m0 + lr + 16 * j) * K + koff0;
            float4 v = *(const float4*)p;
            if (HASA2) {
                const float* p2 = A2 + (size_t)(m0 + lr + 16 * j) * K + koff0;
                float4 v2 = *(const float4*)p2;
                v.x = fmaf(alpha, v2.x, v.x); v.y = fmaf(alpha, v2.y, v.y);
                v.z = fmaf(alpha, v2.z, v.z); v.w = fmaf(alpha, v2.w, v.w);
            }
            av[j] = v;
        }
#pragma unroll
        for (int j = 0; j < 4; j++)
            wv[j] = *(const float4*)(W + (size_t)(n0 + lr + 16 * j) * K + koff0);

        for (int kb = 0; kb < nkb; kb++) {
            float* Ab = gd + (kb & 1) * A_BUF;
            float* Wb = gd + 2 * A_BUF + (kb & 1) * W_BUF;
#pragma unroll
            for (int j = 0; j < 2; j++) stA(Ab, av[j], lkq, lr + 16 * j);
#pragma unroll
            for (int j = 0; j < 4; j++) stW(Wb, wv[j], lkq, lr + 16 * j);
            gbar(grp);
            if (kb + 1 < nkb) {
                int ko = koff0 + (kb + 1) * 32;
#pragma unroll
                for (int j = 0; j < 2; j++) {
                    const float* p = A + (size_t)(m0 + lr + 16 * j) * K + ko;
                    float4 v = *(const float4*)p;
                    if (HASA2) {
                        const float* p2 = A2 + (size_t)(m0 + lr + 16 * j) * K + ko;
                        float4 v2 = *(const float4*)p2;
                        v.x = fmaf(alpha, v2.x, v.x); v.y = fmaf(alpha, v2.y, v.y);
                        v.z = fmaf(alpha, v2.z, v.z); v.w = fmaf(alpha, v2.w, v.w);
                    }
                    av[j] = v;
                }
#pragma unroll
                for (int j = 0; j < 4; j++)
                    wv[j] = *(const float4*)(W + (size_t)(n0 + lr + 16 * j) * K + ko);
            }
            kfma32(Ab, Wb, tx, ty, acc);
        }

        __syncthreads();
        if (grp > 0) red_write(dyn, grp, ltid, acc);
        __syncthreads();
        if (grp == 0) {
            red_accum(dyn, ltid, acc);
            float4 bv = *(const float4*)(bias + n0 + 4 * tx);
#pragma unroll
            for (int r = 0; r < 4; r++) {
                float2 lo = unpack2(acc[r * 2]), hi = unpack2(acc[r * 2 + 1]);
                float4 o = make_float4(lo.x + bv.x, lo.y + bv.y, hi.x + bv.z, hi.y + bv.w);
                if (ACT == 1) {
                    o.x = eluf_(o.x); o.y = eluf_(o.y);
                    o.z = eluf_(o.z); o.w = eluf_(o.w);
                }
                if (ACT == 2) {
                    o.x = fmaxf(o.x, 0.f); o.y = fmaxf(o.y, 0.f);
                    o.z = fmaxf(o.z, 0.f); o.w = fmaxf(o.w, 0.f);
                }
                *(float4*)(C + (size_t)(m0 + 4 * ty + r) * N + n0 + 4 * tx) = o;
            }
        }
        __syncthreads();
    }
}

// ---------------- fused LSTM step ------------------------------------------------
// tile: 32 batch rows x 64 gate-cols (16 hidden units x 4 gates), 128 tiles.
// virtual K = 640 (x:0..127, h:128..639), split-K x4 -> 160 per group (5 kblocks).
__device__ void lstm4(float* dyn, float (*Gs)[64],
                      const float* __restrict__ x, const float* __restrict__ Wih,
                      const float* __restrict__ Whh, const float* __restrict__ bih,
                      const float* __restrict__ bhh, const float* __restrict__ hin,
                      float* __restrict__ hout, int t)
{
    int tid = threadIdx.x;
    int grp = tid >> 7, ltid = tid & 127;
    int tx = ltid & 15, ty = ltid >> 4;
    int lr = ltid >> 3, lkq = ltid & 7;
    float* gd = dyn + grp * GRP_F;
    int h0 = (blockIdx.x & 31) * 16;
    int m0 = (blockIdx.x >> 5) * 32;

    ull acc[8];
#pragma unroll
    for (int i = 0; i < 8; i++) acc[i] = 0;

    float4 av[2], wv[4];
    // loader for virtual k-block kb (0..4): vk0 = grp*160 + kb*32
    auto load = [&](int kb) {
        int vk0 = grp * 160 + kb * 32;
        int isx = vk0 < DD;
        int kp = (isx ? vk0 : vk0 - DD) + lkq * 4;
#pragma unroll
        for (int j = 0; j < 2; j++) {
            int m = m0 + lr + 16 * j;
            const float* p = isx ? (x + ((size_t)m * TT + t) * DD + kp)
                                 : (hin + (size_t)m * HH + kp);
            av[j] = *(const float4*)p;
        }
#pragma unroll
        for (int j = 0; j < 4; j++) {
            int c = lr + 16 * j;
            int wcol = (c >> 4) * HH + h0 + (c & 15);
            const float* p = isx ? (Wih + (size_t)wcol * DD + kp)
                                 : (Whh + (size_t)wcol * HH + kp);
            wv[j] = *(const float4*)p;
        }
    };

    load(0);
    for (int kb = 0; kb < 5; kb++) {
        float* Ab = gd + (kb & 1) * A_BUF;
        float* Wb = gd + 2 * A_BUF + (kb & 1) * W_BUF;
#pragma unroll
        for (int j = 0; j < 2; j++) stA(Ab, av[j], lkq, lr + 16 * j);
#pragma unroll
        for (int j = 0; j < 4; j++) stW(Wb, wv[j], lkq, lr + 16 * j);
        gbar(grp);
        if (kb + 1 < 5) load(kb + 1);
        kfma32(Ab, Wb, tx, ty, acc);
    }

    __syncthreads();
    if (grp > 0) red_write(dyn, grp, ltid, acc);
    __syncthreads();
    if (grp == 0) {
        red_accum(dyn, ltid, acc);
        int bcol = ((4 * tx) >> 4) * HH + h0 + ((4 * tx) & 15);
        float4 bi = *(const float4*)(bih + bcol);
        float4 bh = *(const float4*)(bhh + bcol);
#pragma unroll
        for (int r = 0; r < 4; r++) {
            float2 lo = unpack2(acc[r * 2]), hi = unpack2(acc[r * 2 + 1]);
            float4 o = make_float4(lo.x + bi.x + bh.x, lo.y + bi.y + bh.y,
                                   hi.x + bi.z + bh.z, hi.y + bi.w + bh.w);
            *(float4*)&Gs[4 * ty + r][4 * tx] = o;
        }
    }
    __syncthreads();

    // elementwise c/h update: 512 elems, 1 per thread
    int rr = tid >> 4, jj = tid & 15;
    float iv = sigmoidf_(Gs[rr][jj]);
    float fv = sigmoidf_(Gs[rr][16 + jj]);
    float gv = tanhf(Gs[rr][32 + jj]);
    float ov = sigmoidf_(Gs[rr][48 + jj]);
    int idx = (m0 + rr) * HH + h0 + jj;
    float cn = fv * g_c[idx] + iv * gv;
    g_c[idx] = cn;
    hout[idx] = ov * tanhf(cn);
    __syncthreads();
}

// ---------------- mega persistent kernel (single graph node) --------------------
__global__ __launch_bounds__(NTHR, 1) void mega_kernel(
    const float* __restrict__ x,
    const float* __restrict__ Wih, const float* __restrict__ Whh,
    const float* __restrict__ bih, const float* __restrict__ bhh,
    const float* __restrict__ ow1, const float* __restrict__ ob1,
    const float* __restrict__ ow2, const float* __restrict__ ob2,
    const float* __restrict__ ow3, const float* __restrict__ ob3,
    const float* __restrict__ dw1, const float* __restrict__ db1,
    const float* __restrict__ dw2, const float* __restrict__ db2,
    float* __restrict__ out)
{
    extern __shared__ float dyn[];
    __shared__ float Gs[32][64];

    int tid = threadIdx.x;
    int gidx = blockIdx.x * NTHR + tid;   // 65536 threads == BB*HH

    g_h[0][gidx] = 0.f;
    g_c[gidx] = 0.f;
    gsync();

    // ---- LSTM encoder: 1024 steps ----
    for (int t = 0; t < TT; t++) {
        const float* hin = (t & 1) ? g_h[1] : g_h[0];
        float* hout      = (t & 1) ? g_h[0] : g_h[1];
        lstm4(dyn, Gs, x, Wih, Whh, bih, bhh, hin, hout, t);
        gsync();
    }

    // ---- z0 = c_n; pred slot 0 ----
    {
        float v = g_c[gidx];
        g_z[gidx] = v;
        int bb = gidx >> 9, hh = gidx & 511;
        g_pred[(bb * 5) * HH + hh] = v;
    }
    gsync();

    // ---- latent ODE: 32 RK4 substeps ----
    const double dtd = (5.0 / 60.0) / 8.0;
    const float dtf  = (float)dtd;
    const float half = (float)(0.5 * dtd);
    const float dt6  = (float)(dtd / 6.0);

    for (int step = 0; step < 32; step++) {
        gemm4<1, false>(dyn, g_z, nullptr, 0.f, ow1, ob1, g_t1, BB, NHID, HH); gsync();
        gemm4<1, false>(dyn, g_t1, nullptr, 0.f, ow2, ob2, g_t2, BB, NHID, NHID); gsync();
        gemm4<0, false>(dyn, g_t2, nullptr, 0.f, ow3, ob3, g_k[0], BB, HH, NHID); gsync();

        gemm4<1, true>(dyn, g_z, g_k[0], half, ow1, ob1, g_t1, BB, NHID, HH); gsync();
        gemm4<1, false>(dyn, g_t1, nullptr, 0.f, ow2, ob2, g_t2, BB, NHID, NHID); gsync();
        gemm4<0, false>(dyn, g_t2, nullptr, 0.f, ow3, ob3, g_k[1], BB, HH, NHID); gsync();

        gemm4<1, true>(dyn, g_z, g_k[1], half, ow1, ob1, g_t1, BB, NHID, HH); gsync();
        gemm4<1, false>(dyn, g_t1, nullptr, 0.f, ow2, ob2, g_t2, BB, NHID, NHID); gsync();
        gemm4<0, false>(dyn, g_t2, nullptr, 0.f, ow3, ob3, g_k[2], BB, HH, NHID); gsync();

        gemm4<1, true>(dyn, g_z, g_k[2], dtf, ow1, ob1, g_t1, BB, NHID, HH); gsync();
        gemm4<1, false>(dyn, g_t1, nullptr, 0.f, ow2, ob2, g_t2, BB, NHID, NHID); gsync();
        gemm4<0, false>(dyn, g_t2, nullptr, 0.f, ow3, ob3, g_k[3], BB, HH, NHID); gsync();

        {
            float z = g_z[gidx] + dt6 * (g_k[0][gidx] + 2.f * (g_k[1][gidx] + g_k[2][gidx]) + g_k[3][gidx]);
            g_z[gidx] = z;
            if ((step & 7) == 7) {
                int bb = gidx >> 9, hh = gidx & 511;
                g_pred[(bb * 5 + (step >> 3) + 1) * HH + hh] = z;
            }
        }
        gsync();
    }

    // ---- decoder ----
    gemm4<2, false>(dyn, g_pred, nullptr, 0.f, dw1, db1, g_dec1, BB * 5, NHID, HH);
    gsync();
    gemm4<0, false>(dyn, g_dec1, nullptr, 0.f, dw2, db2, out, BB * 5, DD, NHID);
}

// ---------------- host side -------------------------------------------------------
extern "C" void kernel_launch(void* const* d_in, const int* in_sizes, int n_in,
                              void* d_out, int out_size)
{
    const float* inputs = (const float*)d_in[0];

    // Locate W_ih robustly: 4*512*128 elems followed by 4*512*512.
    int p = 2;
    for (int i = 1; i + 1 < n_in; i++) {
        if (in_sizes[i] == 4 * HH * DD && in_sizes[i + 1] == 4 * HH * HH) { p = i; break; }
    }
    const float* W_ih = (const float*)d_in[p + 0];
    const float* W_hh = (const float*)d_in[p + 1];
    const float* b_ih = (const float*)d_in[p + 2];
    const float* b_hh = (const float*)d_in[p + 3];
    const float* ow1 = (const float*)d_in[p + 4];
    const float* ob1 = (const float*)d_in[p + 5];
    const float* ow2 = (const float*)d_in[p + 6];
    const float* ob2 = (const float*)d_in[p + 7];
    const float* ow3 = (const float*)d_in[p + 8];
    const float* ob3 = (const float*)d_in[p + 9];
    const float* dw1 = (const float*)d_in[p + 10];
    const float* db1 = (const float*)d_in[p + 11];
    const float* dw2 = (const float*)d_in[p + 12];
    const float* db2 = (const float*)d_in[p + 13];

    static int attr_set = 0;
    cudaFuncSetAttribute(mega_kernel, cudaFuncAttributeMaxDynamicSharedMemorySize,
                         DYN_BYTES);
    (void)attr_set;

    mega_kernel<<<GRID, NTHR, DYN_BYTES>>>(inputs, W_ih, W_hh, b_ih, b_hh,
                                           ow1, ob1, ow2, ob2, ow3, ob3,
                                           dw1, db1, dw2, db2, (float*)d_out);
}